// round 5
// baseline (speedup 1.0000x reference)
#include <cuda_runtime.h>
#include <stdint.h>

#define N_NODES 200000
#define N_ETYPES 4
#define N_EDGES 500000
#define DIM 128

// ---------------- scratch (static __device__ — no allocations) ----------------
__device__ float g_Wx[(size_t)N_ETYPES * N_NODES * DIM];   // 409.6 MB
__device__ int   g_cnt[N_ETYPES * N_NODES];
__device__ float g_rinv[N_ETYPES * N_NODES];

// ---------------- kernel 1: zero counts ----------------
__global__ void zero_cnt_kernel() {
    int i = blockIdx.x * blockDim.x + threadIdx.x;
    if (i < N_ETYPES * N_NODES) g_cnt[i] = 0;
}

// ---------------- kernel 2: per-(etype,dst) in-degree ----------------
__global__ void count_kernel(const int* __restrict__ dst) {
    int i = blockIdx.x * blockDim.x + threadIdx.x;
    if (i < N_ETYPES * N_EDGES) {
        int t = i / N_EDGES;
        atomicAdd(&g_cnt[t * N_NODES + dst[i]], 1);
    }
}

// ---------------- kernel 3: reciprocal counts ----------------
__global__ void rinv_kernel() {
    int i = blockIdx.x * blockDim.x + threadIdx.x;
    if (i < N_ETYPES * N_NODES) {
        int c = g_cnt[i];
        g_rinv[i] = (c > 0) ? (1.0f / (float)c) : 0.0f;
    }
}

// ---------------- kernel 4: SGEMM  C[M,128] = x[M,128] @ B[128,128] + bias ----
// blockIdx.y = t in [0,4]: t<4 -> Wx[t] scratch, t==4 -> self message to d_out.
// 128x128 block tile, TK=16, 256 threads, 8x8 micro-tile per thread.
#define TM 128
#define TN 128
#define TK 16

__global__ __launch_bounds__(256)
void gemm_kernel(const float* __restrict__ x,
                 const float* __restrict__ W,
                 const float* __restrict__ b,
                 const float* __restrict__ W_self,
                 const float* __restrict__ b_self,
                 float* __restrict__ out) {
    __shared__ float As[TK][TM];   // A transposed: As[k][row]
    __shared__ float Bs[TK][TN];

    const int bt   = blockIdx.y;
    const int row0 = blockIdx.x * TM;

    const float* Bmat = (bt < 4) ? (W + (size_t)bt * DIM * DIM) : W_self;
    const float* bias = (bt < 4) ? (b + bt * DIM) : b_self;
    float* C = (bt < 4) ? (g_Wx + ((size_t)bt * N_NODES + row0) * DIM)
                        : (out + (size_t)row0 * DIM);

    const int tid = threadIdx.x;
    const int tx  = tid & 15;   // 16 col groups of 8
    const int ty  = tid >> 4;   // 16 row groups of 8

    float acc[8][8];
#pragma unroll
    for (int i = 0; i < 8; i++)
#pragma unroll
        for (int j = 0; j < 8; j++) acc[i][j] = 0.0f;

    for (int kc = 0; kc < DIM; kc += TK) {
        // load A tile: 128 rows x 16 cols = 512 float4, 2 per thread (transposed store)
#pragma unroll
        for (int it = 0; it < 2; it++) {
            int idx = tid + it * 256;
            int r   = idx >> 2;           // 0..127
            int c4  = (idx & 3) * 4;      // 0,4,8,12
            int gr  = row0 + r;
            float4 v = make_float4(0.f, 0.f, 0.f, 0.f);
            if (gr < N_NODES)
                v = *reinterpret_cast<const float4*>(x + (size_t)gr * DIM + kc + c4);
            As[c4 + 0][r] = v.x;
            As[c4 + 1][r] = v.y;
            As[c4 + 2][r] = v.z;
            As[c4 + 3][r] = v.w;
        }
        // load B tile: 16 rows x 128 cols = 512 float4, 2 per thread
#pragma unroll
        for (int it = 0; it < 2; it++) {
            int idx = tid + it * 256;
            int r   = idx >> 5;           // 0..15
            int c4  = (idx & 31) * 4;     // 0..124
            float4 v = *reinterpret_cast<const float4*>(Bmat + (size_t)(kc + r) * DIM + c4);
            *reinterpret_cast<float4*>(&Bs[r][c4]) = v;
        }
        __syncthreads();

#pragma unroll
        for (int k = 0; k < TK; k++) {
            float a[8], bb[8];
#pragma unroll
            for (int i = 0; i < 8; i++) a[i] = As[k][ty * 8 + i];
#pragma unroll
            for (int j = 0; j < 8; j++) bb[j] = Bs[k][tx * 8 + j];
#pragma unroll
            for (int i = 0; i < 8; i++)
#pragma unroll
                for (int j = 0; j < 8; j++) acc[i][j] += a[i] * bb[j];
        }
        __syncthreads();
    }

    // epilogue: add bias, store (bounds-check rows for the tail tile)
#pragma unroll
    for (int i = 0; i < 8; i++) {
        int lr = ty * 8 + i;
        int gr = row0 + lr;
        if (gr >= N_NODES) break;
#pragma unroll
        for (int j = 0; j < 8; j += 4) {
            int c = tx * 8 + j;
            float4 v;
            v.x = acc[i][j + 0] + bias[c + 0];
            v.y = acc[i][j + 1] + bias[c + 1];
            v.z = acc[i][j + 2] + bias[c + 2];
            v.w = acc[i][j + 3] + bias[c + 3];
            *reinterpret_cast<float4*>(C + (size_t)lr * DIM + c) = v;
        }
    }
}

// ---------------- kernel 5: warp-per-edge gather + vector-atomic scatter ------
// out[dst] += Wx[t][src] * (1/cnt[t][dst]); rinv==0 never occurs for real edges.
__global__ __launch_bounds__(256)
void scatter_kernel(const int* __restrict__ src,
                    const int* __restrict__ dst,
                    float* __restrict__ out) {
    int w    = (blockIdx.x * blockDim.x + threadIdx.x) >> 5;
    int lane = threadIdx.x & 31;
    if (w >= N_ETYPES * N_EDGES) return;

    int t = w / N_EDGES;
    int s = __ldg(&src[w]);
    int d = __ldg(&dst[w]);
    float r = g_rinv[t * N_NODES + d];

    const float4* row = reinterpret_cast<const float4*>(
        g_Wx + ((size_t)t * N_NODES + s) * DIM);
    float4 v = row[lane];

    float* p = out + (size_t)d * DIM + lane * 4;
    asm volatile("red.global.add.v4.f32 [%0], {%1, %2, %3, %4};"
                 :: "l"(p), "f"(v.x * r), "f"(v.y * r), "f"(v.z * r), "f"(v.w * r)
                 : "memory");
}

// ---------------- launcher ----------------
extern "C" void kernel_launch(void* const* d_in, const int* in_sizes, int n_in,
                              void* d_out, int out_size) {
    const float* x      = (const float*)d_in[0];   // [200000,128]
    const float* W      = (const float*)d_in[1];   // [4,128,128]
    const float* b      = (const float*)d_in[2];   // [4,128]
    const float* W_self = (const float*)d_in[3];   // [128,128]
    const float* b_self = (const float*)d_in[4];   // [128]
    const int*   src    = (const int*)d_in[5];     // [4,500000]
    const int*   dst    = (const int*)d_in[6];     // [4,500000]
    float* out = (float*)d_out;                    // [200000,128]

    (void)in_sizes; (void)n_in; (void)out_size;

    // 1-3: per-(etype,dst) mean denominators
    {
        int n = N_ETYPES * N_NODES;
        zero_cnt_kernel<<<(n + 255) / 256, 256>>>();
    }
    {
        int n = N_ETYPES * N_EDGES;
        count_kernel<<<(n + 255) / 256, 256>>>(dst);
    }
    {
        int n = N_ETYPES * N_NODES;
        rinv_kernel<<<(n + 255) / 256, 256>>>();
    }

    // 4: 5 GEMMs — Wx[t] to scratch (t=0..3), self message into out (t=4)
    {
        dim3 grid((N_NODES + TM - 1) / TM, 5);
        gemm_kernel<<<grid, 256>>>(x, W, b, W_self, b_self, out);
    }

    // 5: edge scatter with mean scaling (one warp per edge)
    {
        long long warps = (long long)N_ETYPES * N_EDGES;
        long long threads = warps * 32;
        int blocks = (int)((threads + 255) / 256);
        scatter_kernel<<<blocks, 256>>>(src, dst, out);
    }
}

// round 6
// speedup vs baseline: 1.3277x; 1.3277x over previous
#include <cuda_runtime.h>
#include <stdint.h>

#define N_NODES 200000
#define N_ETYPES 4
#define N_EDGES 500000
#define DIM 128

// ---------------- scratch (static __device__ — no allocations) ----------------
__device__ float g_Wx[(size_t)N_ETYPES * N_NODES * DIM];   // 409.6 MB
__device__ int   g_cnt[N_ETYPES * N_NODES];
__device__ float g_rinv[N_ETYPES * N_NODES];

// ---------------- kernel 1: zero counts ----------------
__global__ void zero_cnt_kernel() {
    int i = blockIdx.x * blockDim.x + threadIdx.x;
    if (i < N_ETYPES * N_NODES) g_cnt[i] = 0;
}

// ---------------- kernel 2: per-(etype,dst) in-degree ----------------
__global__ void count_kernel(const int* __restrict__ dst) {
    int i = blockIdx.x * blockDim.x + threadIdx.x;
    if (i < N_ETYPES * N_EDGES) {
        int t = i / N_EDGES;
        atomicAdd(&g_cnt[t * N_NODES + dst[i]], 1);
    }
}

// ---------------- kernel 3: reciprocal counts ----------------
__global__ void rinv_kernel() {
    int i = blockIdx.x * blockDim.x + threadIdx.x;
    if (i < N_ETYPES * N_NODES) {
        int c = g_cnt[i];
        g_rinv[i] = (c > 0) ? (1.0f / (float)c) : 0.0f;
    }
}

// ---------------- kernel 4: TF32 tensor-core GEMM ----------------------------
// C[M,128] = x[M,128] @ B[128,128] + bias, via mma.sync.m16n8k8.tf32.
// blockIdx.y = t in [0,4]: t<4 -> Wx[t] scratch, t==4 -> self message to d_out.
// Block tile 128x128, BK=32, 256 threads = 8 warps in 2(m) x 4(n) grid,
// warp tile 64x32 = 4 m-tiles (m16) x 4 n-tiles (n8).

#define BM 128
#define BK 32
#define A_STRIDE 36    // pad: bank = (4*g + tg) % 32 -> conflict-free frag loads
#define B_STRIDE 136   // pad: bank = (8*tg + g) % 32 -> conflict-free frag loads

__device__ __forceinline__ uint32_t f2tf32(float f) {
    uint32_t u;
    asm("cvt.rna.tf32.f32 %0, %1;" : "=r"(u) : "f"(f));
    return u;
}

__device__ __forceinline__ void mma_tf32(float c[4], const uint32_t a[4],
                                         const uint32_t bb[2]) {
    asm volatile(
        "mma.sync.aligned.m16n8k8.row.col.f32.tf32.tf32.f32 "
        "{%0,%1,%2,%3}, {%4,%5,%6,%7}, {%8,%9}, {%0,%1,%2,%3};"
        : "+f"(c[0]), "+f"(c[1]), "+f"(c[2]), "+f"(c[3])
        : "r"(a[0]), "r"(a[1]), "r"(a[2]), "r"(a[3]), "r"(bb[0]), "r"(bb[1]));
}

__global__ __launch_bounds__(256)
void gemm_tf32_kernel(const float* __restrict__ x,
                      const float* __restrict__ W,
                      const float* __restrict__ b,
                      const float* __restrict__ W_self,
                      const float* __restrict__ b_self,
                      float* __restrict__ out) {
    __shared__ float As[BM][A_STRIDE];   // tf32 bit patterns stored as float
    __shared__ float Bs[BK][B_STRIDE];

    const int bt   = blockIdx.y;
    const int row0 = blockIdx.x * BM;

    const float* Bmat = (bt < 4) ? (W + (size_t)bt * DIM * DIM) : W_self;
    const float* bias = (bt < 4) ? (b + bt * DIM) : b_self;
    float* C = (bt < 4) ? (g_Wx + ((size_t)bt * N_NODES + row0) * DIM)
                        : (out + (size_t)row0 * DIM);

    const int tid  = threadIdx.x;
    const int warp = tid >> 5;
    const int lane = tid & 31;
    const int wm   = warp >> 2;        // 0..1  (64 rows each)
    const int wn   = warp & 3;         // 0..3  (32 cols each)
    const int g    = lane >> 2;        // groupID 0..7
    const int tg   = lane & 3;         // thread-in-group 0..3

    float acc[4][4][4];
#pragma unroll
    for (int i = 0; i < 4; i++)
#pragma unroll
        for (int j = 0; j < 4; j++)
#pragma unroll
            for (int k = 0; k < 4; k++) acc[i][j][k] = 0.0f;

    for (int kc = 0; kc < DIM; kc += BK) {
        // --- load A tile 128x32 (4 float4 per thread), cvt to tf32 ---
#pragma unroll
        for (int it = 0; it < 4; it++) {
            int idx = tid + it * 256;
            int r   = idx >> 3;            // 0..127
            int c4  = (idx & 7) * 4;       // 0..28
            int gr  = row0 + r;
            float4 v = make_float4(0.f, 0.f, 0.f, 0.f);
            if (gr < N_NODES)
                v = *reinterpret_cast<const float4*>(x + (size_t)gr * DIM + kc + c4);
            uint4 t;
            t.x = f2tf32(v.x); t.y = f2tf32(v.y);
            t.z = f2tf32(v.z); t.w = f2tf32(v.w);
            *reinterpret_cast<uint4*>(&As[r][c4]) = t;
        }
        // --- load B tile 32x128 (4 float4 per thread), cvt to tf32 ---
#pragma unroll
        for (int it = 0; it < 4; it++) {
            int idx = tid + it * 256;
            int r   = idx >> 5;            // 0..31
            int c4  = (idx & 31) * 4;      // 0..124
            float4 v = *reinterpret_cast<const float4*>(
                Bmat + (size_t)(kc + r) * DIM + c4);
            uint4 t;
            t.x = f2tf32(v.x); t.y = f2tf32(v.y);
            t.z = f2tf32(v.z); t.w = f2tf32(v.w);
            *reinterpret_cast<uint4*>(&Bs[r][c4]) = t;
        }
        __syncthreads();

#pragma unroll
        for (int ks = 0; ks < BK; ks += 8) {
            uint32_t afr[4][4];
#pragma unroll
            for (int mt = 0; mt < 4; mt++) {
                int r = wm * 64 + mt * 16 + g;
                afr[mt][0] = __float_as_uint(As[r    ][ks + tg    ]);
                afr[mt][1] = __float_as_uint(As[r + 8][ks + tg    ]);
                afr[mt][2] = __float_as_uint(As[r    ][ks + tg + 4]);
                afr[mt][3] = __float_as_uint(As[r + 8][ks + tg + 4]);
            }
            uint32_t bfr[4][2];
#pragma unroll
            for (int nt = 0; nt < 4; nt++) {
                int c = wn * 32 + nt * 8 + g;
                bfr[nt][0] = __float_as_uint(Bs[ks + tg    ][c]);
                bfr[nt][1] = __float_as_uint(Bs[ks + tg + 4][c]);
            }
#pragma unroll
            for (int mt = 0; mt < 4; mt++)
#pragma unroll
                for (int nt = 0; nt < 4; nt++)
                    mma_tf32(acc[mt][nt], afr[mt], bfr[nt]);
        }
        __syncthreads();
    }

    // --- epilogue: bias + store (float2 per acc pair) ---
#pragma unroll
    for (int mt = 0; mt < 4; mt++) {
        int r_lo = wm * 64 + mt * 16 + g;
#pragma unroll
        for (int nt = 0; nt < 4; nt++) {
            int c = wn * 32 + nt * 8 + tg * 2;
            float b0 = bias[c], b1 = bias[c + 1];
            if (row0 + r_lo < N_NODES) {
                float2 v0 = make_float2(acc[mt][nt][0] + b0, acc[mt][nt][1] + b1);
                *reinterpret_cast<float2*>(C + (size_t)r_lo * DIM + c) = v0;
            }
            if (row0 + r_lo + 8 < N_NODES) {
                float2 v1 = make_float2(acc[mt][nt][2] + b0, acc[mt][nt][3] + b1);
                *reinterpret_cast<float2*>(C + (size_t)(r_lo + 8) * DIM + c) = v1;
            }
        }
    }
}

// ---------------- kernel 5: warp-per-edge gather + vector-atomic scatter ------
__global__ __launch_bounds__(256)
void scatter_kernel(const int* __restrict__ src,
                    const int* __restrict__ dst,
                    float* __restrict__ out) {
    int w    = (blockIdx.x * blockDim.x + threadIdx.x) >> 5;
    int lane = threadIdx.x & 31;
    if (w >= N_ETYPES * N_EDGES) return;

    int t = w / N_EDGES;
    int s = __ldg(&src[w]);
    int d = __ldg(&dst[w]);
    float r = g_rinv[t * N_NODES + d];

    const float4* row = reinterpret_cast<const float4*>(
        g_Wx + ((size_t)t * N_NODES + s) * DIM);
    float4 v = row[lane];

    float* p = out + (size_t)d * DIM + lane * 4;
    asm volatile("red.global.add.v4.f32 [%0], {%1, %2, %3, %4};"
                 :: "l"(p), "f"(v.x * r), "f"(v.y * r), "f"(v.z * r), "f"(v.w * r)
                 : "memory");
}

// ---------------- launcher ----------------
extern "C" void kernel_launch(void* const* d_in, const int* in_sizes, int n_in,
                              void* d_out, int out_size) {
    const float* x      = (const float*)d_in[0];   // [200000,128]
    const float* W      = (const float*)d_in[1];   // [4,128,128]
    const float* b      = (const float*)d_in[2];   // [4,128]
    const float* W_self = (const float*)d_in[3];   // [128,128]
    const float* b_self = (const float*)d_in[4];   // [128]
    const int*   src    = (const int*)d_in[5];     // [4,500000]
    const int*   dst    = (const int*)d_in[6];     // [4,500000]
    float* out = (float*)d_out;                    // [200000,128]

    (void)in_sizes; (void)n_in; (void)out_size;

    {
        int n = N_ETYPES * N_NODES;
        zero_cnt_kernel<<<(n + 255) / 256, 256>>>();
    }
    {
        int n = N_ETYPES * N_EDGES;
        count_kernel<<<(n + 255) / 256, 256>>>(dst);
    }
    {
        int n = N_ETYPES * N_NODES;
        rinv_kernel<<<(n + 255) / 256, 256>>>();
    }

    {
        dim3 grid((N_NODES + BM - 1) / BM, 5);
        gemm_tf32_kernel<<<grid, 256>>>(x, W, b, W_self, b_self, out);
    }

    {
        long long warps = (long long)N_ETYPES * N_EDGES;
        long long threads = warps * 32;
        int blocks = (int)((threads + 255) / 256);
        scatter_kernel<<<blocks, 256>>>(src, dst, out);
    }
}

// round 7
// speedup vs baseline: 1.7491x; 1.3174x over previous
#include <cuda_runtime.h>
#include <stdint.h>

#define N_NODES 200000
#define N_ETYPES 4
#define N_EDGES 500000
#define DIM 128

// ---------------- scratch (static __device__ — no allocations) ----------------
__device__ float g_Wx[(size_t)N_ETYPES * N_NODES * DIM];   // 409.6 MB
__device__ int   g_cnt[N_ETYPES * N_NODES];
__device__ float g_rinv[N_ETYPES * N_NODES];

// ---------------- kernel 1: zero counts ----------------
__global__ void zero_cnt_kernel() {
    int i = blockIdx.x * blockDim.x + threadIdx.x;
    if (i < N_ETYPES * N_NODES) g_cnt[i] = 0;
}

// ---------------- kernel 2: per-(etype,dst) in-degree ----------------
__global__ void count_kernel(const int* __restrict__ dst) {
    int i = blockIdx.x * blockDim.x + threadIdx.x;
    if (i < N_ETYPES * N_EDGES) {
        int t = i / N_EDGES;
        atomicAdd(&g_cnt[t * N_NODES + dst[i]], 1);
    }
}

// ---------------- kernel 3: reciprocal counts ----------------
__global__ void rinv_kernel() {
    int i = blockIdx.x * blockDim.x + threadIdx.x;
    if (i < N_ETYPES * N_NODES) {
        int c = g_cnt[i];
        g_rinv[i] = (c > 0) ? (1.0f / (float)c) : 0.0f;
    }
}

// ---------------- kernel 4: fused 5-way TF32 tensor-core GEMM ----------------
// One block owns a 128-row tile of x (tf32 in smem, loaded ONCE), then loops
// bt=0..4 over the 5 weight matrices (4 etypes + self) with cp.async
// double-buffered B tiles. t<4 -> g_Wx[t], t==4 -> self message into d_out.
// 256 threads = 8 warps in 2(m) x 4(n); warp tile 64x32 = 4 m16 x 4 n8.

#define BM 128
#define AS 132    // A smem stride: frag bank = (4g+tg)%32 -> conflict-free
#define BSD 136   // B smem stride: frag bank = (8tg+g)%32 -> conflict-free
#define SMEM_FLOATS (BM * AS + 2 * DIM * BSD)
#define SMEM_BYTES (SMEM_FLOATS * 4)

__device__ __forceinline__ uint32_t f2tf32(float f) {
    uint32_t u;
    asm("cvt.rna.tf32.f32 %0, %1;" : "=r"(u) : "f"(f));
    return u;
}

__device__ __forceinline__ void mma_tf32(float c[4], const uint32_t a[4],
                                         const uint32_t bb[2]) {
    asm volatile(
        "mma.sync.aligned.m16n8k8.row.col.f32.tf32.tf32.f32 "
        "{%0,%1,%2,%3}, {%4,%5,%6,%7}, {%8,%9}, {%0,%1,%2,%3};"
        : "+f"(c[0]), "+f"(c[1]), "+f"(c[2]), "+f"(c[3])
        : "r"(a[0]), "r"(a[1]), "r"(a[2]), "r"(a[3]), "r"(bb[0]), "r"(bb[1]));
}

__device__ __forceinline__ void cp_async_tile(float* sdst,
                                              const float* __restrict__ gsrc,
                                              int tid) {
#pragma unroll
    for (int it = 0; it < 16; it++) {
        int idx = tid + it * 256;
        int r   = idx >> 5;            // 0..127
        int c4  = (idx & 31) * 4;      // 0..124
        uint32_t s = (uint32_t)__cvta_generic_to_shared(sdst + r * BSD + c4);
        asm volatile("cp.async.ca.shared.global [%0], [%1], 16;"
                     :: "r"(s), "l"(gsrc + (size_t)r * DIM + c4));
    }
}

__global__ __launch_bounds__(256)
void gemm_fused_kernel(const float* __restrict__ x,
                       const float* __restrict__ W,
                       const float* __restrict__ b,
                       const float* __restrict__ W_self,
                       const float* __restrict__ b_self,
                       float* __restrict__ out) {
    extern __shared__ float smem[];
    float* As    = smem;                 // [BM][AS], tf32 bit patterns
    float* BsAll = smem + BM * AS;       // [2][DIM][BSD], raw fp32 via cp.async

    const int row0 = blockIdx.x * BM;
    const int tid  = threadIdx.x;
    const int warp = tid >> 5;
    const int lane = tid & 31;
    const int wm   = warp >> 2;        // 0..1
    const int wn   = warp & 3;         // 0..3
    const int g    = lane >> 2;        // 0..7
    const int tg   = lane & 3;         // 0..3

    const float* Bm[5] = {W, W + DIM * DIM, W + 2 * DIM * DIM, W + 3 * DIM * DIM, W_self};
    const float* bi[5] = {b, b + DIM, b + 2 * DIM, b + 3 * DIM, b_self};

    // prefetch B[0] (overlaps the A staging below)
    cp_async_tile(BsAll, Bm[0], tid);
    asm volatile("cp.async.commit_group;");

    // stage A tile once: 128x128 fp32 -> tf32 in smem
#pragma unroll
    for (int it = 0; it < 16; it++) {
        int idx = tid + it * 256;
        int r   = idx >> 5;            // 0..127
        int c4  = (idx & 31) * 4;      // 0..124
        int gr  = row0 + r;
        float4 v = make_float4(0.f, 0.f, 0.f, 0.f);
        if (gr < N_NODES)
            v = *reinterpret_cast<const float4*>(x + (size_t)gr * DIM + c4);
        uint4 t;
        t.x = f2tf32(v.x); t.y = f2tf32(v.y);
        t.z = f2tf32(v.z); t.w = f2tf32(v.w);
        *reinterpret_cast<uint4*>(&As[r * AS + c4]) = t;
    }

    float acc[4][4][4];

    for (int bt = 0; bt < 5; bt++) {
        float* Bbuf = BsAll + (bt & 1) * (DIM * BSD);

        asm volatile("cp.async.wait_group 0;" ::: "memory");
        __syncthreads();   // B[bt] visible; all warps done with other buffer

        if (bt < 4) {
            cp_async_tile(BsAll + ((bt + 1) & 1) * (DIM * BSD), Bm[bt + 1], tid);
            asm volatile("cp.async.commit_group;");
        }

#pragma unroll
        for (int i = 0; i < 4; i++)
#pragma unroll
            for (int j = 0; j < 4; j++)
#pragma unroll
                for (int k = 0; k < 4; k++) acc[i][j][k] = 0.0f;

#pragma unroll
        for (int ks = 0; ks < DIM; ks += 8) {
            uint32_t afr[4][4];
#pragma unroll
            for (int mt = 0; mt < 4; mt++) {
                int r = wm * 64 + mt * 16 + g;
                afr[mt][0] = __float_as_uint(As[r * AS + ks + tg]);
                afr[mt][1] = __float_as_uint(As[(r + 8) * AS + ks + tg]);
                afr[mt][2] = __float_as_uint(As[r * AS + ks + tg + 4]);
                afr[mt][3] = __float_as_uint(As[(r + 8) * AS + ks + tg + 4]);
            }
            uint32_t bfr[4][2];
#pragma unroll
            for (int nt = 0; nt < 4; nt++) {
                int c = wn * 32 + nt * 8 + g;
                bfr[nt][0] = f2tf32(Bbuf[(ks + tg) * BSD + c]);
                bfr[nt][1] = f2tf32(Bbuf[(ks + tg + 4) * BSD + c]);
            }
#pragma unroll
            for (int mt = 0; mt < 4; mt++)
#pragma unroll
                for (int nt = 0; nt < 4; nt++)
                    mma_tf32(acc[mt][nt], afr[mt], bfr[nt]);
        }

        // epilogue for this bt
        const float* bias = bi[bt];
        float* C = (bt < 4) ? (g_Wx + ((size_t)bt * N_NODES + row0) * DIM)
                            : (out + (size_t)row0 * DIM);
#pragma unroll
        for (int nt = 0; nt < 4; nt++) {
            int c = wn * 32 + nt * 8 + tg * 2;
            float b0 = __ldg(&bias[c]);
            float b1 = __ldg(&bias[c + 1]);
#pragma unroll
            for (int mt = 0; mt < 4; mt++) {
                int r_lo = wm * 64 + mt * 16 + g;
                if (row0 + r_lo < N_NODES) {
                    float2 v0 = make_float2(acc[mt][nt][0] + b0,
                                            acc[mt][nt][1] + b1);
                    *reinterpret_cast<float2*>(C + (size_t)r_lo * DIM + c) = v0;
                }
                if (row0 + r_lo + 8 < N_NODES) {
                    float2 v1 = make_float2(acc[mt][nt][2] + b0,
                                            acc[mt][nt][3] + b1);
                    *reinterpret_cast<float2*>(C + (size_t)(r_lo + 8) * DIM + c) = v1;
                }
            }
        }
    }
}

// ---------------- kernel 5: warp-per-edge gather + vector-atomic scatter ------
__global__ __launch_bounds__(256)
void scatter_kernel(const int* __restrict__ src,
                    const int* __restrict__ dst,
                    float* __restrict__ out) {
    int w    = (blockIdx.x * blockDim.x + threadIdx.x) >> 5;
    int lane = threadIdx.x & 31;
    if (w >= N_ETYPES * N_EDGES) return;

    int t = w / N_EDGES;
    int s = __ldg(&src[w]);
    int d = __ldg(&dst[w]);
    float r = g_rinv[t * N_NODES + d];

    const float4* row = reinterpret_cast<const float4*>(
        g_Wx + ((size_t)t * N_NODES + s) * DIM);
    float4 v = row[lane];

    float* p = out + (size_t)d * DIM + lane * 4;
    asm volatile("red.global.add.v4.f32 [%0], {%1, %2, %3, %4};"
                 :: "l"(p), "f"(v.x * r), "f"(v.y * r), "f"(v.z * r), "f"(v.w * r)
                 : "memory");
}

// ---------------- launcher ----------------
extern "C" void kernel_launch(void* const* d_in, const int* in_sizes, int n_in,
                              void* d_out, int out_size) {
    const float* x      = (const float*)d_in[0];   // [200000,128]
    const float* W      = (const float*)d_in[1];   // [4,128,128]
    const float* b      = (const float*)d_in[2];   // [4,128]
    const float* W_self = (const float*)d_in[3];   // [128,128]
    const float* b_self = (const float*)d_in[4];   // [128]
    const int*   src    = (const int*)d_in[5];     // [4,500000]
    const int*   dst    = (const int*)d_in[6];     // [4,500000]
    float* out = (float*)d_out;                    // [200000,128]

    (void)in_sizes; (void)n_in; (void)out_size;

    {
        int n = N_ETYPES * N_NODES;
        zero_cnt_kernel<<<(n + 255) / 256, 256>>>();
    }
    {
        int n = N_ETYPES * N_EDGES;
        count_kernel<<<(n + 255) / 256, 256>>>(dst);
    }
    {
        int n = N_ETYPES * N_NODES;
        rinv_kernel<<<(n + 255) / 256, 256>>>();
    }

    {
        cudaFuncSetAttribute(gemm_fused_kernel,
                             cudaFuncAttributeMaxDynamicSharedMemorySize,
                             SMEM_BYTES);
        int grid = (N_NODES + BM - 1) / BM;
        gemm_fused_kernel<<<grid, 256, SMEM_BYTES>>>(x, W, b, W_self, b_self, out);
    }

    {
        long long warps = (long long)N_ETYPES * N_EDGES;
        long long threads = warps * 32;
        int blocks = (int)((threads + 255) / 256);
        scatter_kernel<<<blocks, 256>>>(src, dst, out);
    }
}

// round 8
// speedup vs baseline: 1.7728x; 1.0136x over previous
#include <cuda_runtime.h>
#include <stdint.h>

#define N_NODES 200000
#define N_ETYPES 4
#define N_EDGES 500000
#define DIM 128

// ---------------- scratch (static __device__ — no allocations) ----------------
__device__ float g_Wx[(size_t)N_ETYPES * N_NODES * DIM];   // 409.6 MB
__device__ int   g_cnt[N_ETYPES * N_NODES];
__device__ float g_rinv[N_ETYPES * N_NODES];

// ---------------- kernel 1: zero counts ----------------
__global__ void zero_cnt_kernel() {
    int i = blockIdx.x * blockDim.x + threadIdx.x;
    if (i < N_ETYPES * N_NODES) g_cnt[i] = 0;
}

// ---------------- kernel 2: per-(etype,dst) in-degree ----------------
__global__ void count_kernel(const int* __restrict__ dst) {
    int i = blockIdx.x * blockDim.x + threadIdx.x;
    if (i < N_ETYPES * N_EDGES) {
        int t = i / N_EDGES;
        atomicAdd(&g_cnt[t * N_NODES + dst[i]], 1);
    }
}

// ---------------- kernel 3: reciprocal counts ----------------
__global__ void rinv_kernel() {
    int i = blockIdx.x * blockDim.x + threadIdx.x;
    if (i < N_ETYPES * N_NODES) {
        int c = g_cnt[i];
        g_rinv[i] = (c > 0) ? (1.0f / (float)c) : 0.0f;
    }
}

// ---------------- kernel 4: fused 5-way TF32 tensor-core GEMM ----------------
// One block owns a 128-row tile of x (tf32 in smem, loaded ONCE), then loops
// bt=0..4 over the 5 weight matrices (4 etypes + self) with cp.async
// double-buffered B tiles. t<4 -> g_Wx[t], t==4 -> self message into d_out.
// 256 threads = 8 warps in 2(m) x 4(n); warp tile 64x32 = 4 m16 x 4 n8.

#define BM 128
#define AS 132    // A smem stride: frag bank = (4g+tg)%32 -> conflict-free
#define BSD 136   // B smem stride: frag bank = (8tg+g)%32 -> conflict-free
#define SMEM_FLOATS (BM * AS + 2 * DIM * BSD)
#define SMEM_BYTES (SMEM_FLOATS * 4)

__device__ __forceinline__ uint32_t f2tf32(float f) {
    uint32_t u;
    asm("cvt.rna.tf32.f32 %0, %1;" : "=r"(u) : "f"(f));
    return u;
}

__device__ __forceinline__ void mma_tf32(float c[4], const uint32_t a[4],
                                         const uint32_t bb[2]) {
    asm volatile(
        "mma.sync.aligned.m16n8k8.row.col.f32.tf32.tf32.f32 "
        "{%0,%1,%2,%3}, {%4,%5,%6,%7}, {%8,%9}, {%0,%1,%2,%3};"
        : "+f"(c[0]), "+f"(c[1]), "+f"(c[2]), "+f"(c[3])
        : "r"(a[0]), "r"(a[1]), "r"(a[2]), "r"(a[3]), "r"(bb[0]), "r"(bb[1]));
}

__device__ __forceinline__ void cp_async_tile(float* sdst,
                                              const float* __restrict__ gsrc,
                                              int tid) {
#pragma unroll
    for (int it = 0; it < 16; it++) {
        int idx = tid + it * 256;
        int r   = idx >> 5;            // 0..127
        int c4  = (idx & 31) * 4;      // 0..124
        uint32_t s = (uint32_t)__cvta_generic_to_shared(sdst + r * BSD + c4);
        asm volatile("cp.async.ca.shared.global [%0], [%1], 16;"
                     :: "r"(s), "l"(gsrc + (size_t)r * DIM + c4));
    }
}

__global__ __launch_bounds__(256)
void gemm_fused_kernel(const float* __restrict__ x,
                       const float* __restrict__ W,
                       const float* __restrict__ b,
                       const float* __restrict__ W_self,
                       const float* __restrict__ b_self,
                       float* __restrict__ out) {
    extern __shared__ float smem[];
    float* As    = smem;                 // [BM][AS], tf32 bit patterns
    float* BsAll = smem + BM * AS;       // [2][DIM][BSD], raw fp32 via cp.async

    const int row0 = blockIdx.x * BM;
    const int tid  = threadIdx.x;
    const int warp = tid >> 5;
    const int lane = tid & 31;
    const int wm   = warp >> 2;        // 0..1
    const int wn   = warp & 3;         // 0..3
    const int g    = lane >> 2;        // 0..7
    const int tg   = lane & 3;         // 0..3

    const float* Bm[5] = {W, W + DIM * DIM, W + 2 * DIM * DIM, W + 3 * DIM * DIM, W_self};
    const float* bi[5] = {b, b + DIM, b + 2 * DIM, b + 3 * DIM, b_self};

    // prefetch B[0] (overlaps the A staging below)
    cp_async_tile(BsAll, Bm[0], tid);
    asm volatile("cp.async.commit_group;");

    // stage A tile once: 128x128 fp32 -> tf32 in smem
#pragma unroll
    for (int it = 0; it < 16; it++) {
        int idx = tid + it * 256;
        int r   = idx >> 5;            // 0..127
        int c4  = (idx & 31) * 4;      // 0..124
        int gr  = row0 + r;
        float4 v = make_float4(0.f, 0.f, 0.f, 0.f);
        if (gr < N_NODES)
            v = *reinterpret_cast<const float4*>(x + (size_t)gr * DIM + c4);
        uint4 t;
        t.x = f2tf32(v.x); t.y = f2tf32(v.y);
        t.z = f2tf32(v.z); t.w = f2tf32(v.w);
        *reinterpret_cast<uint4*>(&As[r * AS + c4]) = t;
    }

    float acc[4][4][4];

    for (int bt = 0; bt < 5; bt++) {
        float* Bbuf = BsAll + (bt & 1) * (DIM * BSD);

        asm volatile("cp.async.wait_group 0;" ::: "memory");
        __syncthreads();   // B[bt] visible; all warps done with other buffer

        if (bt < 4) {
            cp_async_tile(BsAll + ((bt + 1) & 1) * (DIM * BSD), Bm[bt + 1], tid);
            asm volatile("cp.async.commit_group;");
        }

#pragma unroll
        for (int i = 0; i < 4; i++)
#pragma unroll
            for (int j = 0; j < 4; j++)
#pragma unroll
                for (int k = 0; k < 4; k++) acc[i][j][k] = 0.0f;

#pragma unroll
        for (int ks = 0; ks < DIM; ks += 8) {
            uint32_t afr[4][4];
#pragma unroll
            for (int mt = 0; mt < 4; mt++) {
                int r = wm * 64 + mt * 16 + g;
                afr[mt][0] = __float_as_uint(As[r * AS + ks + tg]);
                afr[mt][1] = __float_as_uint(As[(r + 8) * AS + ks + tg]);
                afr[mt][2] = __float_as_uint(As[r * AS + ks + tg + 4]);
                afr[mt][3] = __float_as_uint(As[(r + 8) * AS + ks + tg + 4]);
            }
            uint32_t bfr[4][2];
#pragma unroll
            for (int nt = 0; nt < 4; nt++) {
                int c = wn * 32 + nt * 8 + g;
                bfr[nt][0] = f2tf32(Bbuf[(ks + tg) * BSD + c]);
                bfr[nt][1] = f2tf32(Bbuf[(ks + tg + 4) * BSD + c]);
            }
#pragma unroll
            for (int mt = 0; mt < 4; mt++)
#pragma unroll
                for (int nt = 0; nt < 4; nt++)
                    mma_tf32(acc[mt][nt], afr[mt], bfr[nt]);
        }

        // epilogue for this bt
        const float* bias = bi[bt];
        float* C = (bt < 4) ? (g_Wx + ((size_t)bt * N_NODES + row0) * DIM)
                            : (out + (size_t)row0 * DIM);
#pragma unroll
        for (int nt = 0; nt < 4; nt++) {
            int c = wn * 32 + nt * 8 + tg * 2;
            float b0 = __ldg(&bias[c]);
            float b1 = __ldg(&bias[c + 1]);
#pragma unroll
            for (int mt = 0; mt < 4; mt++) {
                int r_lo = wm * 64 + mt * 16 + g;
                if (row0 + r_lo < N_NODES) {
                    float2 v0 = make_float2(acc[mt][nt][0] + b0,
                                            acc[mt][nt][1] + b1);
                    *reinterpret_cast<float2*>(C + (size_t)r_lo * DIM + c) = v0;
                }
                if (row0 + r_lo + 8 < N_NODES) {
                    float2 v1 = make_float2(acc[mt][nt][2] + b0,
                                            acc[mt][nt][3] + b1);
                    *reinterpret_cast<float2*>(C + (size_t)(r_lo + 8) * DIM + c) = v1;
                }
            }
        }
    }
}

// ---------------- kernel 5: warp-per-edge gather + vector-atomic scatter ------
__global__ __launch_bounds__(256)
void scatter_kernel(const int* __restrict__ src,
                    const int* __restrict__ dst,
                    float* __restrict__ out) {
    int w    = (blockIdx.x * blockDim.x + threadIdx.x) >> 5;
    int lane = threadIdx.x & 31;
    if (w >= N_ETYPES * N_EDGES) return;

    int t = w / N_EDGES;
    int s = __ldg(&src[w]);
    int d = __ldg(&dst[w]);
    float r = g_rinv[t * N_NODES + d];

    const float4* row = reinterpret_cast<const float4*>(
        g_Wx + ((size_t)t * N_NODES + s) * DIM);
    float4 v = row[lane];

    float* p = out + (size_t)d * DIM + lane * 4;
    asm volatile("red.global.add.v4.f32 [%0], {%1, %2, %3, %4};"
                 :: "l"(p), "f"(v.x * r), "f"(v.y * r), "f"(v.z * r), "f"(v.w * r)
                 : "memory");
}

// ---------------- launcher ----------------
extern "C" void kernel_launch(void* const* d_in, const int* in_sizes, int n_in,
                              void* d_out, int out_size) {
    const float* x      = (const float*)d_in[0];   // [200000,128]
    const float* W      = (const float*)d_in[1];   // [4,128,128]
    const float* b      = (const float*)d_in[2];   // [4,128]
    const float* W_self = (const float*)d_in[3];   // [128,128]
    const float* b_self = (const float*)d_in[4];   // [128]
    const int*   src    = (const int*)d_in[5];     // [4,500000]
    const int*   dst    = (const int*)d_in[6];     // [4,500000]
    float* out = (float*)d_out;                    // [200000,128]

    (void)in_sizes; (void)n_in; (void)out_size;

    {
        int n = N_ETYPES * N_NODES;
        zero_cnt_kernel<<<(n + 255) / 256, 256>>>();
    }
    {
        int n = N_ETYPES * N_EDGES;
        count_kernel<<<(n + 255) / 256, 256>>>(dst);
    }
    {
        int n = N_ETYPES * N_NODES;
        rinv_kernel<<<(n + 255) / 256, 256>>>();
    }

    {
        cudaFuncSetAttribute(gemm_fused_kernel,
                             cudaFuncAttributeMaxDynamicSharedMemorySize,
                             SMEM_BYTES);
        int grid = (N_NODES + BM - 1) / BM;
        gemm_fused_kernel<<<grid, 256, SMEM_BYTES>>>(x, W, b, W_self, b_self, out);
    }

    {
        long long warps = (long long)N_ETYPES * N_EDGES;
        long long threads = warps * 32;
        int blocks = (int)((threads + 255) / 256);
        scatter_kernel<<<blocks, 256>>>(src, dst, out);
    }
}